// round 1
// baseline (speedup 1.0000x reference)
#include <cuda_runtime.h>

// Rx(theta) on target qubit 0 == most-significant bit of the 2^24 state index.
// out[0:N]   = real part, out[N:2N] = imag part (stacked [2, 2^24] float32).
//
// Lower half (bit=0):  out0 = c*psi0 - i*s*psi1
// Upper half (bit=1):  out1 = -i*s*psi0 + c*psi1
// with c = cos(theta/2), s = sin(theta/2).
//
// Re/Im split:
//   out_re[k]   = c*re0 + s*im1      out_im[k]   = c*im0 - s*re1
//   out_re[k+H] = c*re1 + s*im0      out_im[k+H] = c*im1 - s*re0

static constexpr int N_QUBITS = 24;
static constexpr int N = 1 << N_QUBITS;        // 2^24
static constexpr int H = N >> 1;               // 2^23 (half)
static constexpr int VEC = 4;                  // float4
static constexpr int NV = H / VEC;             // 2^21 float4s per half
static constexpr int THREADS = 256;

__global__ __launch_bounds__(THREADS)
void rx_gate_kernel(const float* __restrict__ re,
                    const float* __restrict__ im,
                    const float* __restrict__ theta,
                    float* __restrict__ out)
{
    const int i = blockIdx.x * THREADS + threadIdx.x;   // float4 index in [0, NV)
    if (i >= NV) return;

    const float t2 = theta[0] * 0.5f;
    const float c  = __cosf(t2) == __cosf(t2) ? cosf(t2) : cosf(t2); // use precise cosf
    const float s  = sinf(t2);

    const float4* re4 = reinterpret_cast<const float4*>(re);
    const float4* im4 = reinterpret_cast<const float4*>(im);

    // 4 independent 128-bit loads up front (MLP=4)
    const float4 r0 = re4[i];            // re lower half
    const float4 r1 = re4[i + NV];       // re upper half
    const float4 m0 = im4[i];            // im lower half
    const float4 m1 = im4[i + NV];       // im upper half

    float4 oRe0, oRe1, oIm0, oIm1;

    oRe0.x = fmaf(c, r0.x,  s * m1.x);
    oRe0.y = fmaf(c, r0.y,  s * m1.y);
    oRe0.z = fmaf(c, r0.z,  s * m1.z);
    oRe0.w = fmaf(c, r0.w,  s * m1.w);

    oIm0.x = fmaf(c, m0.x, -s * r1.x);
    oIm0.y = fmaf(c, m0.y, -s * r1.y);
    oIm0.z = fmaf(c, m0.z, -s * r1.z);
    oIm0.w = fmaf(c, m0.w, -s * r1.w);

    oRe1.x = fmaf(c, r1.x,  s * m0.x);
    oRe1.y = fmaf(c, r1.y,  s * m0.y);
    oRe1.z = fmaf(c, r1.z,  s * m0.z);
    oRe1.w = fmaf(c, r1.w,  s * m0.w);

    oIm1.x = fmaf(c, m1.x, -s * r0.x);
    oIm1.y = fmaf(c, m1.y, -s * r0.y);
    oIm1.z = fmaf(c, m1.z, -s * r0.z);
    oIm1.w = fmaf(c, m1.w, -s * r0.w);

    float4* outRe = reinterpret_cast<float4*>(out);          // out[0:N]
    float4* outIm = reinterpret_cast<float4*>(out + N);      // out[N:2N]

    outRe[i]      = oRe0;
    outRe[i + NV] = oRe1;
    outIm[i]      = oIm0;
    outIm[i + NV] = oIm1;
}

extern "C" void kernel_launch(void* const* d_in, const int* in_sizes, int n_in,
                              void* d_out, int out_size)
{
    const float* re    = (const float*)d_in[0];
    const float* im    = (const float*)d_in[1];
    const float* theta = (const float*)d_in[2];
    float* out = (float*)d_out;

    const int blocks = NV / THREADS;   // 2^21 / 256 = 8192
    rx_gate_kernel<<<blocks, THREADS>>>(re, im, theta, out);
}

// round 2
// speedup vs baseline: 1.0057x; 1.0057x over previous
#include <cuda_runtime.h>

// Rx(theta) on the MSB qubit of a 2^24 state vector.
// out[0:N] = real, out[N:2N] = imag.
//   out_re[k]   = c*re0 + s*im1      out_im[k]   = c*im0 - s*re1
//   out_re[k+H] = c*re1 + s*im0      out_im[k+H] = c*im1 - s*re0
// c = cos(theta/2), s = sin(theta/2).
//
// Streaming kernel: all loads __ldcs, all stores __stcs (evict-first),
// 2 float4 groups per thread per stream (8 front-batched LDG.128).

static constexpr int N_QUBITS = 24;
static constexpr int N  = 1 << N_QUBITS;   // 2^24
static constexpr int H  = N >> 1;          // 2^23
static constexpr int NV = H / 4;           // 2^21 float4 per half
static constexpr int THREADS = 256;
static constexpr int ITEMS = 2;            // float4 groups per thread per stream
static constexpr int BLOCKS = NV / (THREADS * ITEMS);   // 4096

__device__ __forceinline__ float4 ld_cs4(const float4* p) {
    return __ldcs(p);
}
__device__ __forceinline__ void st_cs4(float4* p, float4 v) {
    __stcs(p, v);
}

__global__ __launch_bounds__(THREADS)
void rx_gate_kernel(const float* __restrict__ re,
                    const float* __restrict__ im,
                    const float* __restrict__ theta,
                    float* __restrict__ out)
{
    const float t2 = theta[0] * 0.5f;
    const float c  = cosf(t2);
    const float s  = sinf(t2);
    const float ns = -s;

    const float4* re4 = reinterpret_cast<const float4*>(re);
    const float4* im4 = reinterpret_cast<const float4*>(im);
    float4* outRe = reinterpret_cast<float4*>(out);
    float4* outIm = reinterpret_cast<float4*>(out + N);

    // base index for this thread's first group; groups are THREADS apart
    const int base = blockIdx.x * (THREADS * ITEMS) + threadIdx.x;

    float4 r0[ITEMS], r1[ITEMS], m0[ITEMS], m1[ITEMS];

    // front-batch all 8 loads (MLP=8)
    #pragma unroll
    for (int j = 0; j < ITEMS; j++) {
        const int i = base + j * THREADS;
        r0[j] = ld_cs4(re4 + i);
        r1[j] = ld_cs4(re4 + i + NV);
        m0[j] = ld_cs4(im4 + i);
        m1[j] = ld_cs4(im4 + i + NV);
    }

    #pragma unroll
    for (int j = 0; j < ITEMS; j++) {
        const int i = base + j * THREADS;
        float4 oRe0, oRe1, oIm0, oIm1;

        oRe0.x = fmaf(c, r0[j].x, s * m1[j].x);
        oRe0.y = fmaf(c, r0[j].y, s * m1[j].y);
        oRe0.z = fmaf(c, r0[j].z, s * m1[j].z);
        oRe0.w = fmaf(c, r0[j].w, s * m1[j].w);

        oIm0.x = fmaf(c, m0[j].x, ns * r1[j].x);
        oIm0.y = fmaf(c, m0[j].y, ns * r1[j].y);
        oIm0.z = fmaf(c, m0[j].z, ns * r1[j].z);
        oIm0.w = fmaf(c, m0[j].w, ns * r1[j].w);

        oRe1.x = fmaf(c, r1[j].x, s * m0[j].x);
        oRe1.y = fmaf(c, r1[j].y, s * m0[j].y);
        oRe1.z = fmaf(c, r1[j].z, s * m0[j].z);
        oRe1.w = fmaf(c, r1[j].w, s * m0[j].w);

        oIm1.x = fmaf(c, m1[j].x, ns * r0[j].x);
        oIm1.y = fmaf(c, m1[j].y, ns * r0[j].y);
        oIm1.z = fmaf(c, m1[j].z, ns * r0[j].z);
        oIm1.w = fmaf(c, m1[j].w, ns * r0[j].w);

        st_cs4(outRe + i,      oRe0);
        st_cs4(outRe + i + NV, oRe1);
        st_cs4(outIm + i,      oIm0);
        st_cs4(outIm + i + NV, oIm1);
    }
}

extern "C" void kernel_launch(void* const* d_in, const int* in_sizes, int n_in,
                              void* d_out, int out_size)
{
    const float* re    = (const float*)d_in[0];
    const float* im    = (const float*)d_in[1];
    const float* theta = (const float*)d_in[2];
    float* out = (float*)d_out;

    rx_gate_kernel<<<BLOCKS, THREADS>>>(re, im, theta, out);
}